// round 8
// baseline (speedup 1.0000x reference)
#include <cuda_runtime.h>

// ALIF forward: x_seq [T, n_flat] -> spikes [T, n_flat]. HBM-bound streaming
// recurrence (536 MB traffic, zero reuse).
//  - float2: 2 neuron columns/thread, LDG.64/STG.64, 2 independent chains.
//  - Depth-3 rotating prefetch (UNROLL=8 x 3 buffers), outer loop unrolled x3:
//    two groups (16 float2 = 128 B/thread, 4 MB chip-wide) are ALWAYS in
//    flight while the third is computed -> smooth load-issue cadence.
//  - __ldcs / __stcs streaming hints: evict-first, keep L2 from thrashing.
//  - 32768 threads, block=32 -> 1024 CTAs -> 6.92/SM balance (max 7).

static constexpr int T_STEPS = 1024;
static constexpr int U = 8;          // time steps per buffer group

__global__ __launch_bounds__(32)
void ALIF_24309514895931_kernel(
    const float2* __restrict__ x,     // [T, n2]
    const float2* __restrict__ v0,    // [n2]
    const float2* __restrict__ a0,    // [n2]
    const float* __restrict__ p_decay_v,
    const float* __restrict__ p_decay_a,
    const float* __restrict__ p_threshold,
    const float* __restrict__ p_beta,
    float2* __restrict__ out,         // [T, n2]
    int n2)                           // n_flat / 2
{
    const int i = blockIdx.x * blockDim.x + threadIdx.x;
    if (i >= n2) return;

    const float dv   = *p_decay_v;
    const float da   = *p_decay_a;
    const float thr  = *p_threshold;
    const float beta = *p_beta;

    float2 v = v0[i];
    float2 a = a0[i];

    const float2* xp = x + i;
    float2*       op = out + i;
    const int stride = n2;            // max index T*n2 = 33.5M -> 32-bit safe

    float2 bufA[U], bufB[U], bufC[U];

    // Prologue: fill A (t=0) and B (t=U).
    #pragma unroll
    for (int u = 0; u < U; u++) bufA[u] = __ldcs(&xp[u * stride]);
    #pragma unroll
    for (int u = 0; u < U; u++) bufB[u] = __ldcs(&xp[(U + u) * stride]);

    // Body macro: prefetch group (t + 2U) into PRE, compute+store group t
    // from CUR. Two groups stay in flight while CUR is consumed.
#define ALIF_STAGE(tcur, PRE, CUR)                                         \
    {                                                                       \
        const int pf = (tcur) + 2 * U;                                      \
        if (pf < T_STEPS) {                                                 \
            const int base = pf * stride;                                   \
            _Pragma("unroll")                                               \
            for (int u = 0; u < U; u++)                                     \
                PRE[u] = __ldcs(&xp[base + u * stride]);                    \
        }                                                                   \
        const int obase = (tcur) * stride;                                  \
        _Pragma("unroll")                                                   \
        for (int u = 0; u < U; u++) {                                       \
            float2 xv = CUR[u];                                             \
            float2 s;                                                       \
            v.x = fmaf(dv, v.x, xv.x);                                      \
            v.y = fmaf(dv, v.y, xv.y);                                      \
            float thx = fmaf(beta, a.x, thr);                               \
            float thy = fmaf(beta, a.y, thr);                               \
            s.x = (v.x > thx) ? 1.0f : 0.0f;                                \
            s.y = (v.y > thy) ? 1.0f : 0.0f;                                \
            v.x = fmaf(-s.x, thx, v.x);                                     \
            v.y = fmaf(-s.y, thy, v.y);                                     \
            a.x = fmaf(da, a.x, s.x);                                       \
            a.y = fmaf(da, a.y, s.y);                                       \
            __stcs(&op[obase + u * stride], s);                             \
        }                                                                   \
    }

    // T_STEPS / U = 128 groups; outer loop unrolled x3 over the rotation.
    // 128 = 3*42 + 2 -> handle 126 groups in the rotating loop, then 2 tail
    // groups (whose prefetches were skipped by the pf < T_STEPS guard).
    #pragma unroll 1
    for (int t = 0; t < (T_STEPS - 2 * U); t += 3 * U) {
        ALIF_STAGE(t,         bufC, bufA);   // prefetch t+2U into C, consume A
        ALIF_STAGE(t + U,     bufA, bufB);   // prefetch t+3U into A, consume B
        ALIF_STAGE(t + 2 * U, bufB, bufC);   // prefetch t+4U into B, consume C
    }
    // Tail: groups at t = 1008-U*? -> after loop, t = 1008; remaining groups
    // 1008 (in A) and 1016 (in B). (126 groups done; rotation left A,B full.)
    ALIF_STAGE(T_STEPS - 2 * U, bufC, bufA);
    ALIF_STAGE(T_STEPS - U,     bufC, bufB);
#undef ALIF_STAGE
}

extern "C" void kernel_launch(void* const* d_in, const int* in_sizes, int n_in,
                              void* d_out, int out_size) {
    const float* x     = (const float*)d_in[0];
    const float* v0    = (const float*)d_in[1];
    const float* a0    = (const float*)d_in[2];
    const float* dv    = (const float*)d_in[3];
    const float* da    = (const float*)d_in[4];
    const float* thr   = (const float*)d_in[5];
    const float* beta  = (const float*)d_in[6];
    // d_in[7] = alpha: unused in forward pass.

    const int n_flat = in_sizes[1];
    const int n2 = n_flat / 2;        // n_flat = 65536, even

    dim3 block(32);
    dim3 grid((n2 + 31) / 32);
    ALIF_24309514895931_kernel<<<grid, block>>>(
        (const float2*)x, (const float2*)v0, (const float2*)a0,
        dv, da, thr, beta, (float2*)d_out, n2);
}

// round 9
// speedup vs baseline: 1.1827x; 1.1827x over previous
#include <cuda_runtime.h>

// ALIF forward: x_seq [T, n_flat] -> spikes [T, n_flat]. HBM-bound streaming
// recurrence (536 MB traffic, zero reuse). R9 = R7 ping-pong structure with
// ONE change: prefetch of the next 16-step group is interleaved one LDG per
// recurrence step (instead of a 16-load burst), smoothing load-issue cadence
// so in-flight bytes stay near the 4 MB peak instead of sawtoothing.
//  - float2: 2 neuron columns/thread, 2 independent recurrence chains.
//  - 32768 threads, block=32 -> 1024 CTAs -> 6.92/SM balance (max 7).

static constexpr int T_STEPS = 1024;
static constexpr int U = 16;         // time steps per group

__global__ __launch_bounds__(32)
void ALIF_24309514895931_kernel(
    const float2* __restrict__ x,     // [T, n2]
    const float2* __restrict__ v0,    // [n2]
    const float2* __restrict__ a0,    // [n2]
    const float* __restrict__ p_decay_v,
    const float* __restrict__ p_decay_a,
    const float* __restrict__ p_threshold,
    const float* __restrict__ p_beta,
    float2* __restrict__ out,         // [T, n2]
    int n2)                           // n_flat / 2
{
    const int i = blockIdx.x * blockDim.x + threadIdx.x;
    if (i >= n2) return;

    const float dv   = *p_decay_v;
    const float da   = *p_decay_a;
    const float thr  = *p_threshold;
    const float beta = *p_beta;

    float2 v = v0[i];
    float2 a = a0[i];

    const float2* xp = x + i;
    float2*       op = out + i;
    const int stride = n2;            // max index T*n2 = 33.5M -> 32-bit safe

    float2 bufA[U], bufB[U];

    // Prologue: A <- group 0 (burst; nothing to overlap with yet).
    #pragma unroll
    for (int u = 0; u < U; u++) bufA[u] = xp[u * stride];
    // B <- group 1 (burst).
    #pragma unroll
    for (int u = 0; u < U; u++) bufB[u] = xp[(U + u) * stride];

    // One stage: consume CUR (group tcur); per step also issue one prefetch
    // LDG for group tcur+2U into CUR (it is free as soon as step u reads it).
#define ALIF_STAGE(tcur, CUR, DO_PREFETCH)                                  \
    {                                                                       \
        const int obase = (tcur) * stride;                                  \
        const int pbase = ((tcur) + 2 * U) * stride;                        \
        _Pragma("unroll")                                                   \
        for (int u = 0; u < U; u++) {                                       \
            float2 xv = CUR[u];                                             \
            if (DO_PREFETCH)                                                \
                CUR[u] = xp[pbase + u * stride];                            \
            float2 s;                                                       \
            v.x = fmaf(dv, v.x, xv.x);                                      \
            v.y = fmaf(dv, v.y, xv.y);                                      \
            float thx = fmaf(beta, a.x, thr);                               \
            float thy = fmaf(beta, a.y, thr);                               \
            s.x = (v.x > thx) ? 1.0f : 0.0f;                                \
            s.y = (v.y > thy) ? 1.0f : 0.0f;                                \
            v.x = fmaf(-s.x, thx, v.x);                                     \
            v.y = fmaf(-s.y, thy, v.y);                                     \
            a.x = fmaf(da, a.x, s.x);                                       \
            a.y = fmaf(da, a.y, s.y);                                       \
            op[obase + u * stride] = s;                                     \
        }                                                                   \
    }

    // 64 groups of U=16. Main loop handles groups 0..61 (31 iterations of
    // A,B), each stage prefetching group t+2U. Last two groups (62, 63 at
    // t = 992, 1008) consume without prefetch.
    #pragma unroll 1
    for (int t = 0; t < T_STEPS - 2 * U; t += 2 * U) {
        ALIF_STAGE(t,     bufA, true);    // consume A(t),   A <- t+2U
        ALIF_STAGE(t + U, bufB, true);    // consume B(t+U), B <- t+3U
    }
    ALIF_STAGE(T_STEPS - 2 * U, bufA, false);
    ALIF_STAGE(T_STEPS - U,     bufB, false);
#undef ALIF_STAGE
}

extern "C" void kernel_launch(void* const* d_in, const int* in_sizes, int n_in,
                              void* d_out, int out_size) {
    const float* x     = (const float*)d_in[0];
    const float* v0    = (const float*)d_in[1];
    const float* a0    = (const float*)d_in[2];
    const float* dv    = (const float*)d_in[3];
    const float* da    = (const float*)d_in[4];
    const float* thr   = (const float*)d_in[5];
    const float* beta  = (const float*)d_in[6];
    // d_in[7] = alpha: unused in forward pass.

    const int n_flat = in_sizes[1];
    const int n2 = n_flat / 2;        // n_flat = 65536, even

    dim3 block(32);
    dim3 grid((n2 + 31) / 32);
    ALIF_24309514895931_kernel<<<grid, block>>>(
        (const float2*)x, (const float2*)v0, (const float2*)a0,
        dv, da, thr, beta, (float2*)d_out, n2);
}